// round 1
// baseline (speedup 1.0000x reference)
#include <cuda_runtime.h>

#define U_N 200000
#define M_N 100000
#define E_N 2000000
#define EL_N 500000
#define HD 64
#define CN 7

// ---------------- device scratch (static, no runtime allocation) ----------------
__device__ int d_flag64;
__device__ int d_deg_u[U_N];
__device__ int d_deg_m[M_N];
__device__ int d_off_u[U_N + 1];
__device__ int d_off_m[M_N + 1];
__device__ int d_cur_u[U_N];
__device__ int d_cur_m[M_N];
__device__ int d_nbr_u[E_N];   // per-user neighbor movie ids
__device__ int d_nbr_m[E_N];   // per-movie neighbor user ids
__device__ int d_part[1024];
__device__ float d_xu[(size_t)U_N * HD];
__device__ float d_xm[(size_t)M_N * HD];
__device__ float d_u1[(size_t)U_N * HD];
__device__ float d_m1[(size_t)M_N * HD];
__device__ float d_u2[(size_t)U_N * HD];
__device__ float d_m2[(size_t)M_N * HD];

// index loader: handles int64 (x64-enabled reference) or int32 silently-downcast
__device__ __forceinline__ int ldidx(const void* p, int i) {
    return d_flag64 ? (int)((const long long*)p)[i] : ((const int*)p)[i];
}

// ---------------- detect index width from user_node_id (= arange) ----------------
__global__ void k_detect(const int* unid_words) {
    // int64 arange: element 1 = words {1,0}; word[3] = high word of element1 = 0
    // int32 arange: word[3] = value 3 != 0
    d_flag64 = (unid_words[3] == 0) ? 1 : 0;
}

__global__ void k_zero_deg() {
    int i = blockIdx.x * blockDim.x + threadIdx.x;
    if (i < U_N) d_deg_u[i] = 0;
    else if (i < U_N + M_N) d_deg_m[i - U_N] = 0;
}

__global__ void k_count(const void* es, const void* ed, int n) {
    for (int e = blockIdx.x * blockDim.x + threadIdx.x; e < n;
         e += gridDim.x * blockDim.x) {
        int s = ldidx(es, e);
        int d = ldidx(ed, e);
        atomicAdd(&d_deg_u[s], 1);
        atomicAdd(&d_deg_m[d], 1);
    }
}

// ---------------- exclusive scan: (deg of length n_real, virtual 0 at n_real) -> off[n_real+1]
__global__ void k_scan_sum(const int* deg, int n_real, int n_tot, int* part) {
    __shared__ int sh[256];
    int base = blockIdx.x * 2048 + threadIdx.x * 8;
    int s = 0;
#pragma unroll
    for (int r = 0; r < 8; r++) {
        int i = base + r;
        int v = (i < n_real) ? deg[i] : 0;
        if (i < n_tot) s += v;
    }
    sh[threadIdx.x] = s;
    __syncthreads();
    for (int o = 128; o > 0; o >>= 1) {
        if (threadIdx.x < o) sh[threadIdx.x] += sh[threadIdx.x + o];
        __syncthreads();
    }
    if (threadIdx.x == 0) part[blockIdx.x] = sh[0];
}

__global__ void k_scan_part(int* part, int nb) {
    __shared__ int sh[1024];
    int t = threadIdx.x;
    int v = (t < nb) ? part[t] : 0;
    sh[t] = v;
    __syncthreads();
    for (int o = 1; o < 1024; o <<= 1) {
        int a = (t >= o) ? sh[t - o] : 0;
        __syncthreads();
        sh[t] += a;
        __syncthreads();
    }
    if (t < nb) part[t] = sh[t] - v;  // exclusive
}

__global__ void k_scan_out(const int* deg, int n_real, int n_tot,
                           const int* part, int* off) {
    __shared__ int sh[256];
    int tid = threadIdx.x;
    int base = blockIdx.x * 2048 + tid * 8;
    int vals[8];
    int s = 0;
#pragma unroll
    for (int r = 0; r < 8; r++) {
        int i = base + r;
        int v = (i < n_real) ? deg[i] : 0;
        vals[r] = s;
        if (i < n_tot) s += v;
    }
    sh[tid] = s;
    __syncthreads();
    int tot = s;
    for (int o = 1; o < 256; o <<= 1) {
        int a = (tid >= o) ? sh[tid - o] : 0;
        __syncthreads();
        sh[tid] += a;
        __syncthreads();
    }
    int tbase = sh[tid] - tot + part[blockIdx.x];
#pragma unroll
    for (int r = 0; r < 8; r++) {
        int i = base + r;
        if (i < n_tot) off[i] = tbase + vals[r];
    }
}

__global__ void k_initcur() {
    int i = blockIdx.x * blockDim.x + threadIdx.x;
    if (i < U_N) d_cur_u[i] = d_off_u[i];
    else if (i < U_N + M_N) d_cur_m[i - U_N] = d_off_m[i - U_N];
}

__global__ void k_fill(const void* es, const void* ed, int n) {
    for (int e = blockIdx.x * blockDim.x + threadIdx.x; e < n;
         e += gridDim.x * blockDim.x) {
        int s = ldidx(es, e);
        int d = ldidx(ed, e);
        int pu = atomicAdd(&d_cur_u[s], 1);
        d_nbr_u[pu] = d;
        int pm = atomicAdd(&d_cur_m[d], 1);
        d_nbr_m[pm] = s;
    }
}

// ---------------- input projections ----------------
__global__ void k_gather_user(const void* unid, const float* ue) {
    int n4 = U_N * (HD / 4);
    for (int j = blockIdx.x * blockDim.x + threadIdx.x; j < n4;
         j += gridDim.x * blockDim.x) {
        int node = j >> 4;
        int q = j & 15;
        int uid = ldidx(unid, node);
        reinterpret_cast<float4*>(d_xu)[j] =
            reinterpret_cast<const float4*>(ue)[(size_t)uid * 16 + q];
    }
}

// xm = movie_x @ w_movie + b_movie + movie_emb[movie_node_id]
__global__ void k_movie_proj(const void* mnid, const float* mx, const float* W,
                             const float* b, const float* memb, int M, int F) {
    __shared__ float2 sW[32 * 32];  // F <= 32
    for (int idx = threadIdx.x; idx < F * 32; idx += blockDim.x) {
        int f = idx >> 5, t = idx & 31;
        sW[idx] = make_float2(W[f * HD + t], W[f * HD + t + 32]);
    }
    __syncthreads();
    int lane = threadIdx.x & 31;
    int warp = threadIdx.x >> 5;
    for (int m = blockIdx.x * 8 + warp; m < M; m += gridDim.x * 8) {
        float mxv = (lane < F) ? mx[(size_t)m * F + lane] : 0.f;
        int mid = ldidx(mnid, m);
        float acc0 = b[lane] + memb[(size_t)mid * HD + lane];
        float acc1 = b[lane + 32] + memb[(size_t)mid * HD + lane + 32];
        for (int f = 0; f < F; f++) {
            float v = __shfl_sync(0xffffffffu, mxv, f);
            float2 wv = sW[f * 32 + lane];
            acc0 += v * wv.x;
            acc1 += v * wv.y;
        }
        d_xm[(size_t)m * HD + lane] = acc0;
        d_xm[(size_t)m * HD + lane + 32] = acc1;
    }
}

// ---------------- fused SAGE: out = [mean_agg(xs over nbrs)]@Wl + bl + xd@Wr (+relu)
__global__ __launch_bounds__(256) void k_sage(const float* __restrict__ xs,
                                              const float* __restrict__ xd,
                                              const int* __restrict__ off,
                                              const int* __restrict__ nbr,
                                              int n_dst,
                                              const float* __restrict__ Wl,
                                              const float* __restrict__ bl,
                                              const float* __restrict__ Wr,
                                              float* __restrict__ out,
                                              int doRelu) {
    __shared__ float2 sWl[HD * 32];
    __shared__ float2 sWr[HD * 32];
    __shared__ float sb[HD];
    __shared__ float sst[8][128];  // per-warp: [agg(64) | xd(64)]

    for (int idx = threadIdx.x; idx < HD * 32; idx += blockDim.x) {
        int k = idx >> 5, t = idx & 31;
        sWl[idx] = make_float2(Wl[k * HD + t], Wl[k * HD + t + 32]);
        sWr[idx] = make_float2(Wr[k * HD + t], Wr[k * HD + t + 32]);
    }
    if (threadIdx.x < HD) sb[threadIdx.x] = bl[threadIdx.x];
    __syncthreads();

    int lane = threadIdx.x & 31;
    int warp = threadIdx.x >> 5;
    float* st = sst[warp];

    for (int i = blockIdx.x * 8 + warp; i < n_dst; i += gridDim.x * 8) {
        int s0 = off[i], s1 = off[i + 1];
        int deg = s1 - s0;
        float inv = 1.f / (float)max(deg, 1);
        float a0 = 0.f, a1 = 0.f;
        for (int j = s0; j < s1; j += 32) {
            int myn = (j + lane < s1) ? nbr[j + lane] : 0;
            int cnt = min(32, s1 - j);
            for (int jj = 0; jj < cnt; jj++) {
                int nn = __shfl_sync(0xffffffffu, myn, jj);
                const float* r = xs + (size_t)nn * HD;
                a0 += r[lane];
                a1 += r[lane + 32];
            }
        }
        a0 *= inv;
        a1 *= inv;
        st[lane] = a0;
        st[lane + 32] = a1;
        st[64 + lane] = xd[(size_t)i * HD + lane];
        st[96 + lane] = xd[(size_t)i * HD + lane + 32];
        __syncwarp();

        float acc0 = sb[lane], acc1 = sb[lane + 32];
#pragma unroll 8
        for (int k = 0; k < HD; k++) {
            float va = st[k];
            float vx = st[64 + k];
            float2 wl = sWl[k * 32 + lane];
            float2 wr = sWr[k * 32 + lane];
            acc0 += va * wl.x + vx * wr.x;
            acc1 += va * wl.y + vx * wr.y;
        }
        __syncwarp();
        if (doRelu) {
            acc0 = fmaxf(acc0, 0.f);
            acc1 = fmaxf(acc1, 0.f);
        }
        out[(size_t)i * HD + lane] = acc0;
        out[(size_t)i * HD + lane + 32] = acc1;
    }
}

// ---------------- edge classifier: concat(u2[s], m2[d]) @ cls_W + cls_b ----------------
__global__ __launch_bounds__(256) void k_classify(const void* els, const void* eld,
                                                  const float* __restrict__ W,
                                                  const float* __restrict__ b,
                                                  float* __restrict__ out, int EL) {
    int lane = threadIdx.x & 31;
    int warp = threadIdx.x >> 5;
    // per-lane weight registers: feats {lane, 32+lane, 64+lane, 96+lane}
    float rw0[CN], rw1[CN], rw2[CN], rw3[CN], rb[CN];
#pragma unroll
    for (int c = 0; c < CN; c++) {
        rw0[c] = W[lane * CN + c];
        rw1[c] = W[(32 + lane) * CN + c];
        rw2[c] = W[(64 + lane) * CN + c];
        rw3[c] = W[(96 + lane) * CN + c];
        rb[c] = b[c];
    }
    for (int e = blockIdx.x * 8 + warp; e < EL; e += gridDim.x * 8) {
        int s = ldidx(els, e);
        int d = ldidx(eld, e);
        float f0 = d_u2[(size_t)s * HD + lane];
        float f1 = d_u2[(size_t)s * HD + lane + 32];
        float f2 = d_m2[(size_t)d * HD + lane];
        float f3 = d_m2[(size_t)d * HD + lane + 32];
        float acc[CN];
#pragma unroll
        for (int c = 0; c < CN; c++)
            acc[c] = f0 * rw0[c] + f1 * rw1[c] + f2 * rw2[c] + f3 * rw3[c];
#pragma unroll
        for (int o = 16; o > 0; o >>= 1) {
#pragma unroll
            for (int c = 0; c < CN; c++)
                acc[c] += __shfl_down_sync(0xffffffffu, acc[c], o);
        }
        if (lane == 0) {
#pragma unroll
            for (int c = 0; c < CN; c++) out[(size_t)e * CN + c] = acc[c] + rb[c];
        }
    }
}

// ---------------- host launch ----------------
extern "C" void kernel_launch(void* const* d_in, const int* in_sizes, int n_in,
                              void* d_out, int out_size) {
    const void* unid = d_in[0];
    const void* mnid = d_in[1];
    const float* movie_x = (const float*)d_in[2];
    const void* esrc = d_in[3];
    const void* edst = d_in[4];
    const void* elsrc = d_in[5];
    const void* eldst = d_in[6];
    const float* user_emb = (const float*)d_in[7];
    const float* w_movie = (const float*)d_in[9];
    const float* b_movie = (const float*)d_in[10];
    const float* movie_emb = (const float*)d_in[8];

    int U = in_sizes[0];
    int M = in_sizes[1];
    int E = in_sizes[3];
    int EL = in_sizes[5];
    int F = in_sizes[2] / M;
    (void)n_in; (void)out_size;

    void *p_deg_u, *p_deg_m, *p_off_u, *p_off_m, *p_part;
    cudaGetSymbolAddress(&p_deg_u, d_deg_u);
    cudaGetSymbolAddress(&p_deg_m, d_deg_m);
    cudaGetSymbolAddress(&p_off_u, d_off_u);
    cudaGetSymbolAddress(&p_off_m, d_off_m);
    cudaGetSymbolAddress(&p_part, d_part);

    // 1. index-width detect
    k_detect<<<1, 1>>>((const int*)unid);

    // 2. CSR build
    k_zero_deg<<<(U + M + 255) / 256, 256>>>();
    k_count<<<2048, 256>>>(esrc, edst, E);

    int NBu = (U + 1 + 2047) / 2048;
    int NBm = (M + 1 + 2047) / 2048;
    k_scan_sum<<<NBu, 256>>>((const int*)p_deg_u, U, U + 1, (int*)p_part);
    k_scan_part<<<1, 1024>>>((int*)p_part, NBu);
    k_scan_out<<<NBu, 256>>>((const int*)p_deg_u, U, U + 1, (const int*)p_part,
                             (int*)p_off_u);
    k_scan_sum<<<NBm, 256>>>((const int*)p_deg_m, M, M + 1, (int*)p_part);
    k_scan_part<<<1, 1024>>>((int*)p_part, NBm);
    k_scan_out<<<NBm, 256>>>((const int*)p_deg_m, M, M + 1, (const int*)p_part,
                             (int*)p_off_m);

    k_initcur<<<(U + M + 255) / 256, 256>>>();
    k_fill<<<2048, 256>>>(esrc, edst, E);

    // 3. input projections
    k_gather_user<<<(U * 16 + 255) / 256, 256>>>(unid, user_emb);
    k_movie_proj<<<1024, 256>>>(mnid, movie_x, w_movie, b_movie, movie_emb, M, F);

    // device pointers to feature scratch
    void *p_xu, *p_xm, *p_u1, *p_m1, *p_u2, *p_m2, *p_nbr_u, *p_nbr_m;
    cudaGetSymbolAddress(&p_xu, d_xu);
    cudaGetSymbolAddress(&p_xm, d_xm);
    cudaGetSymbolAddress(&p_u1, d_u1);
    cudaGetSymbolAddress(&p_m1, d_m1);
    cudaGetSymbolAddress(&p_u2, d_u2);
    cudaGetSymbolAddress(&p_m2, d_m2);
    cudaGetSymbolAddress(&p_nbr_u, d_nbr_u);
    cudaGetSymbolAddress(&p_nbr_m, d_nbr_m);

    const int SB = 1480;  // grid-stride blocks for sage kernels

    // 4. layer 1 (relu)
    // u1 = relu(mean_agg(x_movie over user's movie nbrs) @ l1_rev_Wl + bl + x_user @ l1_rev_Wr)
    k_sage<<<SB, 256>>>((const float*)p_xm, (const float*)p_xu, (const int*)p_off_u,
                        (const int*)p_nbr_u, U, (const float*)d_in[14],
                        (const float*)d_in[15], (const float*)d_in[16],
                        (float*)p_u1, 1);
    // m1 = relu(mean_agg(x_user over movie's user nbrs) @ l1_rates_Wl + bl + x_movie @ l1_rates_Wr)
    k_sage<<<SB, 256>>>((const float*)p_xu, (const float*)p_xm, (const int*)p_off_m,
                        (const int*)p_nbr_m, M, (const float*)d_in[11],
                        (const float*)d_in[12], (const float*)d_in[13],
                        (float*)p_m1, 1);

    // 5. layer 2 (no activation)
    k_sage<<<SB, 256>>>((const float*)p_m1, (const float*)p_u1, (const int*)p_off_u,
                        (const int*)p_nbr_u, U, (const float*)d_in[20],
                        (const float*)d_in[21], (const float*)d_in[22],
                        (float*)p_u2, 0);
    k_sage<<<SB, 256>>>((const float*)p_u1, (const float*)p_m1, (const int*)p_off_m,
                        (const int*)p_nbr_m, M, (const float*)d_in[17],
                        (const float*)d_in[18], (const float*)d_in[19],
                        (float*)p_m2, 0);

    // 6. classifier
    k_classify<<<2048, 256>>>(elsrc, eldst, (const float*)d_in[23],
                              (const float*)d_in[24], (float*)d_out, EL);
}

// round 2
// speedup vs baseline: 1.1289x; 1.1289x over previous
#include <cuda_runtime.h>

#define U_N 200000
#define M_N 100000
#define E_N 2000000
#define HD 64
#define CN 7

// ---------------- device scratch ----------------
__device__ int d_deg_u[U_N];
__device__ int d_deg_m[M_N];
__device__ int d_off_u[U_N + 1];
__device__ int d_off_m[M_N + 1];
__device__ int d_cur_u[U_N];
__device__ int d_cur_m[M_N];
__device__ int d_nbr_u[E_N];
__device__ int d_nbr_m[E_N];
__device__ int d_part[256];
__device__ float d_xu[(size_t)U_N * HD];
__device__ float d_xm[(size_t)M_N * HD];
__device__ float d_u1[(size_t)U_N * HD];
__device__ float d_m1[(size_t)M_N * HD];
__device__ float d_u2[(size_t)U_N * HD];
__device__ float d_m2[(size_t)M_N * HD];

// index loader: int64 (x64 reference) or int32 (silent downcast)
__device__ __forceinline__ int ldidx(const void* p, int i, int f64) {
    return f64 ? (int)((const long long*)p)[i] : ((const int*)p)[i];
}
// detect width from user_node_id (= arange): int64 -> word[3] (hi of elem 1) == 0
__device__ __forceinline__ int detect64(const int* uw) { return uw[3] == 0; }

// ---------------- launch 1: zero degrees + user gather + movie projection ----------------
__global__ __launch_bounds__(256) void k_prep(
    const int* uw, const void* unid, const void* mnid,
    const float* ue, const float* mx, const float* W, const float* bb,
    const float* memb, int U, int M, int F, int GZ, int GG, int GM) {
    __shared__ float2 sW[32 * 32];
    int f64 = detect64(uw);
    if ((int)blockIdx.x < GZ) {
        int i = blockIdx.x * 256 + threadIdx.x;
        if (i < U) d_deg_u[i] = 0;
        else if (i < U + M) d_deg_m[i - U] = 0;
    } else if ((int)blockIdx.x < GZ + GG) {
        int j = (blockIdx.x - GZ) * 256 + threadIdx.x;
        if (j < U * 16) {
            int node = j >> 4, q = j & 15;
            int uid = ldidx(unid, node, f64);
            reinterpret_cast<float4*>(d_xu)[j] =
                reinterpret_cast<const float4*>(ue)[(size_t)uid * 16 + q];
        }
    } else {
        for (int idx = threadIdx.x; idx < F * 32; idx += 256) {
            int f = idx >> 5, t = idx & 31;
            sW[idx] = make_float2(W[f * HD + t], W[f * HD + t + 32]);
        }
        __syncthreads();
        int lane = threadIdx.x & 31, warp = threadIdx.x >> 5;
        int mb = blockIdx.x - (GZ + GG);
        for (int m = mb * 8 + warp; m < M; m += GM * 8) {
            float mxv = (lane < F) ? mx[(size_t)m * F + lane] : 0.f;
            int mid = ldidx(mnid, m, f64);
            float acc0 = bb[lane] + memb[(size_t)mid * HD + lane];
            float acc1 = bb[lane + 32] + memb[(size_t)mid * HD + lane + 32];
            for (int f = 0; f < F; f++) {
                float v = __shfl_sync(0xffffffffu, mxv, f);
                float2 wv = sW[f * 32 + lane];
                acc0 += v * wv.x;
                acc1 += v * wv.y;
            }
            d_xm[(size_t)m * HD + lane] = acc0;
            d_xm[(size_t)m * HD + lane + 32] = acc1;
        }
    }
}

// ---------------- launch 2: degree count ----------------
__global__ void k_count(const int* uw, const void* es, const void* ed, int n) {
    int f64 = detect64(uw);
    for (int e = blockIdx.x * blockDim.x + threadIdx.x; e < n;
         e += gridDim.x * blockDim.x) {
        atomicAdd(&d_deg_u[ldidx(es, e, f64)], 1);
        atomicAdd(&d_deg_m[ldidx(ed, e, f64)], 1);
    }
}

// ---------------- launch 3: per-block sums (u blocks then m blocks) ----------------
__global__ void k_scan_sum(int U, int M, int NBu) {
    __shared__ int sh[256];
    int isU = (int)blockIdx.x < NBu;
    const int* deg = isU ? d_deg_u : d_deg_m;
    int n_real = isU ? U : M;
    int n_tot = n_real + 1;
    int rb = isU ? blockIdx.x : blockIdx.x - NBu;
    int base = rb * 2048 + threadIdx.x * 8;
    int s = 0;
#pragma unroll
    for (int r = 0; r < 8; r++) {
        int i = base + r;
        int v = (i < n_real) ? deg[i] : 0;
        if (i < n_tot) s += v;
    }
    sh[threadIdx.x] = s;
    __syncthreads();
    for (int o = 128; o > 0; o >>= 1) {
        if ((int)threadIdx.x < o) sh[threadIdx.x] += sh[threadIdx.x + o];
        __syncthreads();
    }
    if (threadIdx.x == 0) d_part[blockIdx.x] = sh[0];
}

// ---------------- launch 4: scan-out (redundant base reduce) + cursor init ----------------
__global__ void k_scan_out(int U, int M, int NBu) {
    __shared__ int sh[256];
    __shared__ int sp[256];
    int tid = threadIdx.x;
    int isU = (int)blockIdx.x < NBu;
    const int* deg = isU ? d_deg_u : d_deg_m;
    int* off = isU ? d_off_u : d_off_m;
    int* cur = isU ? d_cur_u : d_cur_m;
    int n_real = isU ? U : M;
    int n_tot = n_real + 1;
    int rb = isU ? blockIdx.x : blockIdx.x - NBu;
    int lo = isU ? 0 : NBu;

    // base = sum of predecessor block sums within this partition
    sp[tid] = (tid >= lo && tid < (int)blockIdx.x) ? d_part[tid] : 0;
    __syncthreads();
    for (int o = 128; o > 0; o >>= 1) {
        if (tid < o) sp[tid] += sp[tid + o];
        __syncthreads();
    }
    int base0 = sp[0];
    __syncthreads();

    int base = rb * 2048 + tid * 8;
    int vals[8];
    int s = 0;
#pragma unroll
    for (int r = 0; r < 8; r++) {
        int i = base + r;
        int v = (i < n_real) ? deg[i] : 0;
        vals[r] = s;
        if (i < n_tot) s += v;
    }
    sh[tid] = s;
    __syncthreads();
    int tot = s;
    for (int o = 1; o < 256; o <<= 1) {
        int a = (tid >= o) ? sh[tid - o] : 0;
        __syncthreads();
        sh[tid] += a;
        __syncthreads();
    }
    int tbase = sh[tid] - tot + base0;
#pragma unroll
    for (int r = 0; r < 8; r++) {
        int i = base + r;
        if (i < n_tot) {
            int v = tbase + vals[r];
            off[i] = v;
            if (i < n_real) cur[i] = v;
        }
    }
}

// ---------------- launch 5: fill adjacency ----------------
__global__ void k_fill(const int* uw, const void* es, const void* ed, int n) {
    int f64 = detect64(uw);
    for (int e = blockIdx.x * blockDim.x + threadIdx.x; e < n;
         e += gridDim.x * blockDim.x) {
        int s = ldidx(es, e, f64);
        int d = ldidx(ed, e, f64);
        d_nbr_u[atomicAdd(&d_cur_u[s], 1)] = d;
        d_nbr_m[atomicAdd(&d_cur_m[d], 1)] = s;
    }
}

// ---------------- launches 6-9: fused SAGE ----------------
// out = mean_agg(xs over nbrs) @ Wl + bl + xd @ Wr  (+relu)
// lane owns output cols {2l, 2l+1}; agg/xd held in registers, bcast via shfl.
__device__ __forceinline__ float2 gather_row(const float* __restrict__ xs,
                                             const int* __restrict__ nbr,
                                             int s0, int s1, int lane) {
    float a0 = 0.f, a1 = 0.f;
    for (int j = s0; j < s1; j += 32) {
        int myn = (j + lane < s1) ? nbr[j + lane] : 0;
        int cnt = min(32, s1 - j);
        int jj = 0;
        for (; jj + 4 <= cnt; jj += 4) {
            int n0 = __shfl_sync(0xffffffffu, myn, jj);
            int n1 = __shfl_sync(0xffffffffu, myn, jj + 1);
            int n2 = __shfl_sync(0xffffffffu, myn, jj + 2);
            int n3 = __shfl_sync(0xffffffffu, myn, jj + 3);
            float2 r0 = *reinterpret_cast<const float2*>(xs + (size_t)n0 * HD + 2 * lane);
            float2 r1 = *reinterpret_cast<const float2*>(xs + (size_t)n1 * HD + 2 * lane);
            float2 r2 = *reinterpret_cast<const float2*>(xs + (size_t)n2 * HD + 2 * lane);
            float2 r3 = *reinterpret_cast<const float2*>(xs + (size_t)n3 * HD + 2 * lane);
            a0 += (r0.x + r1.x) + (r2.x + r3.x);
            a1 += (r0.y + r1.y) + (r2.y + r3.y);
        }
        for (; jj < cnt; jj++) {
            int nn = __shfl_sync(0xffffffffu, myn, jj);
            float2 r = *reinterpret_cast<const float2*>(xs + (size_t)nn * HD + 2 * lane);
            a0 += r.x;
            a1 += r.y;
        }
    }
    float inv = 1.f / (float)max(s1 - s0, 1);
    return make_float2(a0 * inv, a1 * inv);
}

__global__ __launch_bounds__(256) void k_sage(const float* __restrict__ xs,
                                              const float* __restrict__ xd,
                                              const int* __restrict__ off,
                                              const int* __restrict__ nbr,
                                              int n_dst,
                                              const float* __restrict__ Wl,
                                              const float* __restrict__ bl,
                                              const float* __restrict__ Wr,
                                              float* __restrict__ out,
                                              int doRelu) {
    __shared__ float4 sWl[32 * 32];  // [kpair][lane] = {W[2kp][2l],W[2kp][2l+1],W[2kp+1][2l],W[2kp+1][2l+1]}
    __shared__ float4 sWr[32 * 32];
    __shared__ float sb[HD];

    for (int idx = threadIdx.x; idx < 32 * 32; idx += blockDim.x) {
        int kp = idx >> 5, l = idx & 31;
        sWl[idx] = make_float4(Wl[(2 * kp) * HD + 2 * l], Wl[(2 * kp) * HD + 2 * l + 1],
                               Wl[(2 * kp + 1) * HD + 2 * l], Wl[(2 * kp + 1) * HD + 2 * l + 1]);
        sWr[idx] = make_float4(Wr[(2 * kp) * HD + 2 * l], Wr[(2 * kp) * HD + 2 * l + 1],
                               Wr[(2 * kp + 1) * HD + 2 * l], Wr[(2 * kp + 1) * HD + 2 * l + 1]);
    }
    if (threadIdx.x < HD) sb[threadIdx.x] = bl[threadIdx.x];
    __syncthreads();

    int lane = threadIdx.x & 31, warp = threadIdx.x >> 5;
    float b0 = sb[2 * lane], b1 = sb[2 * lane + 1];

    for (int i0 = (blockIdx.x * 8 + warp) * 2; i0 < n_dst; i0 += gridDim.x * 16) {
        int hasB = (i0 + 1 < n_dst);
        int sA0 = off[i0], sA1 = off[i0 + 1];
        float2 aggA = gather_row(xs, nbr, sA0, sA1, lane);
        float2 aggB = make_float2(0.f, 0.f);
        float2 xdB = make_float2(0.f, 0.f);
        if (hasB) {
            int sB0 = off[i0 + 1], sB1 = off[i0 + 2];
            aggB = gather_row(xs, nbr, sB0, sB1, lane);
            xdB = *reinterpret_cast<const float2*>(xd + (size_t)(i0 + 1) * HD + 2 * lane);
        }
        float2 xdA = *reinterpret_cast<const float2*>(xd + (size_t)i0 * HD + 2 * lane);

        float pA0 = b0, pA1 = b1, pB0 = b0, pB1 = b1;
#pragma unroll 8
        for (int kp = 0; kp < 32; kp++) {
            float4 wl = sWl[kp * 32 + lane];
            float4 wr = sWr[kp * 32 + lane];
            float aA0 = __shfl_sync(0xffffffffu, aggA.x, kp);
            float aA1 = __shfl_sync(0xffffffffu, aggA.y, kp);
            float xA0 = __shfl_sync(0xffffffffu, xdA.x, kp);
            float xA1 = __shfl_sync(0xffffffffu, xdA.y, kp);
            float aB0 = __shfl_sync(0xffffffffu, aggB.x, kp);
            float aB1 = __shfl_sync(0xffffffffu, aggB.y, kp);
            float xB0 = __shfl_sync(0xffffffffu, xdB.x, kp);
            float xB1 = __shfl_sync(0xffffffffu, xdB.y, kp);
            pA0 += aA0 * wl.x + aA1 * wl.z + xA0 * wr.x + xA1 * wr.z;
            pA1 += aA0 * wl.y + aA1 * wl.w + xA0 * wr.y + xA1 * wr.w;
            pB0 += aB0 * wl.x + aB1 * wl.z + xB0 * wr.x + xB1 * wr.z;
            pB1 += aB0 * wl.y + aB1 * wl.w + xB0 * wr.y + xB1 * wr.w;
        }
        if (doRelu) {
            pA0 = fmaxf(pA0, 0.f); pA1 = fmaxf(pA1, 0.f);
            pB0 = fmaxf(pB0, 0.f); pB1 = fmaxf(pB1, 0.f);
        }
        *reinterpret_cast<float2*>(out + (size_t)i0 * HD + 2 * lane) = make_float2(pA0, pA1);
        if (hasB)
            *reinterpret_cast<float2*>(out + (size_t)(i0 + 1) * HD + 2 * lane) = make_float2(pB0, pB1);
    }
}

// ---------------- launch 10: edge classifier ----------------
__global__ __launch_bounds__(256) void k_classify(const int* uw, const void* els,
                                                  const void* eld,
                                                  const float* __restrict__ W,
                                                  const float* __restrict__ b,
                                                  float* __restrict__ out, int EL) {
    int f64 = detect64(uw);
    int lane = threadIdx.x & 31, warp = threadIdx.x >> 5;
    float w0[CN], w1[CN], w2[CN], w3[CN];
#pragma unroll
    for (int c = 0; c < CN; c++) {
        w0[c] = W[(2 * lane) * CN + c];
        w1[c] = W[(2 * lane + 1) * CN + c];
        w2[c] = W[(HD + 2 * lane) * CN + c];
        w3[c] = W[(HD + 2 * lane + 1) * CN + c];
    }
    for (int e = blockIdx.x * 8 + warp; e < EL; e += gridDim.x * 8) {
        int s = ldidx(els, e, f64);
        int d = ldidx(eld, e, f64);
        float2 fu = *reinterpret_cast<const float2*>(d_u2 + (size_t)s * HD + 2 * lane);
        float2 fm = *reinterpret_cast<const float2*>(d_m2 + (size_t)d * HD + 2 * lane);
        float acc[CN];
#pragma unroll
        for (int c = 0; c < CN; c++)
            acc[c] = fu.x * w0[c] + fu.y * w1[c] + fm.x * w2[c] + fm.y * w3[c];
#pragma unroll
        for (int o = 16; o > 0; o >>= 1) {
#pragma unroll
            for (int c = 0; c < CN; c++)
                acc[c] += __shfl_down_sync(0xffffffffu, acc[c], o);
        }
        if (lane == 0) {
#pragma unroll
            for (int c = 0; c < CN; c++) out[(size_t)e * CN + c] = acc[c] + b[c];
        }
    }
}

// ---------------- host launch ----------------
extern "C" void kernel_launch(void* const* d_in, const int* in_sizes, int n_in,
                              void* d_out, int out_size) {
    const int* uw = (const int*)d_in[0];
    const void* unid = d_in[0];
    const void* mnid = d_in[1];
    const float* movie_x = (const float*)d_in[2];
    const void* esrc = d_in[3];
    const void* edst = d_in[4];
    const void* elsrc = d_in[5];
    const void* eldst = d_in[6];
    const float* user_emb = (const float*)d_in[7];
    const float* movie_emb = (const float*)d_in[8];
    const float* w_movie = (const float*)d_in[9];
    const float* b_movie = (const float*)d_in[10];

    int U = in_sizes[0];
    int M = in_sizes[1];
    int E = in_sizes[3];
    int EL = in_sizes[5];
    int F = in_sizes[2] / M;
    (void)n_in; (void)out_size;

    void *p_off_u, *p_off_m, *p_nbr_u, *p_nbr_m;
    void *p_xu, *p_xm, *p_u1, *p_m1, *p_u2, *p_m2;
    cudaGetSymbolAddress(&p_off_u, d_off_u);
    cudaGetSymbolAddress(&p_off_m, d_off_m);
    cudaGetSymbolAddress(&p_nbr_u, d_nbr_u);
    cudaGetSymbolAddress(&p_nbr_m, d_nbr_m);
    cudaGetSymbolAddress(&p_xu, d_xu);
    cudaGetSymbolAddress(&p_xm, d_xm);
    cudaGetSymbolAddress(&p_u1, d_u1);
    cudaGetSymbolAddress(&p_m1, d_m1);
    cudaGetSymbolAddress(&p_u2, d_u2);
    cudaGetSymbolAddress(&p_m2, d_m2);

    // launch 1: prep (zero deg + gather user + movie proj)
    int GZ = (U + M + 255) / 256;
    int GG = (U * 16 + 255) / 256;
    int GM = 1024;
    k_prep<<<GZ + GG + GM, 256>>>(uw, unid, mnid, user_emb, movie_x, w_movie,
                                  b_movie, movie_emb, U, M, F, GZ, GG, GM);
    // launch 2: count
    k_count<<<2048, 256>>>(uw, esrc, edst, E);
    // launches 3-4: scans (u and m fused)
    int NBu = (U + 1 + 2047) / 2048;
    int NBm = (M + 1 + 2047) / 2048;
    k_scan_sum<<<NBu + NBm, 256>>>(U, M, NBu);
    k_scan_out<<<NBu + NBm, 256>>>(U, M, NBu);
    // launch 5: fill
    k_fill<<<2048, 256>>>(uw, esrc, edst, E);

    const int SB = 1480;
    // launches 6-9: SAGE layers (launch 6 is the ncu capture target)
    k_sage<<<SB, 256>>>((const float*)p_xm, (const float*)p_xu, (const int*)p_off_u,
                        (const int*)p_nbr_u, U, (const float*)d_in[14],
                        (const float*)d_in[15], (const float*)d_in[16],
                        (float*)p_u1, 1);
    k_sage<<<SB, 256>>>((const float*)p_xu, (const float*)p_xm, (const int*)p_off_m,
                        (const int*)p_nbr_m, M, (const float*)d_in[11],
                        (const float*)d_in[12], (const float*)d_in[13],
                        (float*)p_m1, 1);
    k_sage<<<SB, 256>>>((const float*)p_m1, (const float*)p_u1, (const int*)p_off_u,
                        (const int*)p_nbr_u, U, (const float*)d_in[20],
                        (const float*)d_in[21], (const float*)d_in[22],
                        (float*)p_u2, 0);
    k_sage<<<SB, 256>>>((const float*)p_u1, (const float*)p_m1, (const int*)p_off_m,
                        (const int*)p_nbr_m, M, (const float*)d_in[17],
                        (const float*)d_in[18], (const float*)d_in[19],
                        (float*)p_m2, 0);
    // launch 10: classifier
    k_classify<<<2048, 256>>>(uw, elsrc, eldst, (const float*)d_in[23],
                              (const float*)d_in[24], (float*)d_out, EL);
}